// round 2
// baseline (speedup 1.0000x reference)
#include <cuda_runtime.h>
#include <cuda_bf16.h>
#include <math.h>

// ---------------- problem constants ----------------
#define BB 8
#define TT 2048
#define DD 128
#define HH 4
#define HD 32
#define DH 64
#define NTOK (BB*TT)
#define SCALE 0.17677669529663687f
#define LAMBDA_INIT 0.8f
#define LN_EPS 1e-5f
#define BAND 96

// ---------------- scratch ----------------
__device__ float g_xnorm[NTOK * DD];
__device__ float g_Q[BB*HH*TT*DH];
__device__ float g_K[BB*HH*TT*DH];
__device__ float g_V[BB*HH*TT*DH];
__device__ float g_O[NTOK * 256];

__device__ __forceinline__ float redmax8(float v){
    v = fmaxf(v, __shfl_xor_sync(0xffffffffu, v, 1));
    v = fmaxf(v, __shfl_xor_sync(0xffffffffu, v, 2));
    v = fmaxf(v, __shfl_xor_sync(0xffffffffu, v, 4));
    return v;
}
__device__ __forceinline__ float redsum8(float v){
    v += __shfl_xor_sync(0xffffffffu, v, 1);
    v += __shfl_xor_sync(0xffffffffu, v, 2);
    v += __shfl_xor_sync(0xffffffffu, v, 4);
    return v;
}

// ================= K0: layernorm =================
__global__ __launch_bounds__(256) void ln_kernel(const float* __restrict__ x,
                                                 const float* __restrict__ w,
                                                 const float* __restrict__ b){
    int token = blockIdx.x * 8 + threadIdx.y;
    int lane  = threadIdx.x;
    const float4* xr = (const float4*)(x + (size_t)token * DD);
    float4 v = xr[lane];
    float s = v.x + v.y + v.z + v.w;
    #pragma unroll
    for (int o = 16; o; o >>= 1) s += __shfl_xor_sync(0xffffffffu, s, o);
    float mu = s * (1.0f / DD);
    float dx0 = v.x - mu, dx1 = v.y - mu, dx2 = v.z - mu, dx3 = v.w - mu;
    float sq = dx0*dx0 + dx1*dx1 + dx2*dx2 + dx3*dx3;
    #pragma unroll
    for (int o = 16; o; o >>= 1) sq += __shfl_xor_sync(0xffffffffu, sq, o);
    float rstd = rsqrtf(sq * (1.0f / DD) + LN_EPS);
    float4 wv = ((const float4*)w)[lane];
    float4 bv = ((const float4*)b)[lane];
    float4 out;
    out.x = dx0 * rstd * wv.x + bv.x;
    out.y = dx1 * rstd * wv.y + bv.y;
    out.z = dx2 * rstd * wv.z + bv.z;
    out.w = dx3 * rstd * wv.w + bv.w;
    ((float4*)(g_xnorm + (size_t)token * DD))[lane] = out;
}

// ================= K1: QKV GEMM (16384 x 768 x 128), 128x128x16, 8x8 micro =================
#define QAS 132
#define QBS 132
__global__ __launch_bounds__(256) void qkv_gemm(const float* __restrict__ wq,
                                                const float* __restrict__ wk,
                                                const float* __restrict__ wv){
    __shared__ float As[16*QAS];   // [k][m]
    __shared__ float Bs[16*QBS];   // [k][n]
    int brow = blockIdx.x;         // 0..127
    int bc   = blockIdx.y;         // 0..5
    int tid = threadIdx.x;
    int tr = tid >> 4, tc = tid & 15;
    const float* W = (bc < 2) ? wq : (bc < 4 ? wk : wv);
    int colbase = (bc & 1) * 128;
    float acc[8][8] = {};

    for (int kc = 0; kc < 8; kc++){
        #pragma unroll
        for (int f = tid; f < 512; f += 256){
            int r = f >> 2, c4 = f & 3;
            float4 v = *(const float4*)(g_xnorm + (size_t)(brow*128 + r)*DD + kc*16 + c4*4);
            As[(c4*4+0)*QAS + r] = v.x;
            As[(c4*4+1)*QAS + r] = v.y;
            As[(c4*4+2)*QAS + r] = v.z;
            As[(c4*4+3)*QAS + r] = v.w;
        }
        #pragma unroll
        for (int f = tid; f < 512; f += 256){
            int kr = f >> 5, c4 = f & 31;
            float4 v = *(const float4*)(W + (size_t)(kc*16 + kr)*256 + colbase + c4*4);
            *(float4*)(Bs + kr*QBS + c4*4) = v;
        }
        __syncthreads();
        #pragma unroll
        for (int k = 0; k < 16; k++){
            float a[8], bbv[8];
            *(float4*)(a)   = *(const float4*)(As + k*QAS + tr*8);
            *(float4*)(a+4) = *(const float4*)(As + k*QAS + tr*8 + 4);
            *(float4*)(bbv)   = *(const float4*)(Bs + k*QBS + tc*8);
            *(float4*)(bbv+4) = *(const float4*)(Bs + k*QBS + tc*8 + 4);
            #pragma unroll
            for (int i = 0; i < 8; i++)
                #pragma unroll
                for (int j = 0; j < 8; j++)
                    acc[i][j] += a[i] * bbv[j];
        }
        __syncthreads();
    }

    int mat = bc >> 1;
    float* dst = (mat == 0) ? g_Q : (mat == 1 ? g_K : g_V);
    int col = colbase + tc*8;
    int head = col >> 6, dim = col & 63;
    #pragma unroll
    for (int i = 0; i < 8; i++){
        int token = brow*128 + tr*8 + i;
        int b_ = token >> 11, t = token & (TT-1);
        float* drow = dst + ((size_t)((b_*HH + head)*TT + t))*DH + dim;
        *(float4*)(drow)   = make_float4(acc[i][0], acc[i][1], acc[i][2], acc[i][3]);
        *(float4*)(drow+4) = make_float4(acc[i][4], acc[i][5], acc[i][6], acc[i][7]);
    }
}

// ================= K2: banded dual-softmax flash attention (vectorized) =================
#define SQS 68
#define SKS 36
#define SVS 68
#define SPS 68
#define SM_Q1 0
#define SM_Q2 (32*SQS)
#define SM_K1 (2*32*SQS)
#define SM_K2 (SM_K1 + 32*SKS)
#define SM_V  (SM_K2 + 32*SKS)
#define SM_P1 (SM_V + 32*SVS)
#define SM_P2 (SM_P1 + 32*SPS)
#define ATTN_SMEM_FLOATS (SM_P2 + 32*SPS)
#define ATTN_SMEM_BYTES (ATTN_SMEM_FLOATS * 4)

__global__ __launch_bounds__(128) void attn_kernel(
        const float* __restrict__ lq1, const float* __restrict__ lk1,
        const float* __restrict__ lq2, const float* __restrict__ lk2,
        const float* __restrict__ sig_s_p, const float* __restrict__ sig_n_p,
        const float* __restrict__ hnw, const float* __restrict__ hnb){
    extern __shared__ float sm[];
    float* sq1 = sm + SM_Q1;   // [32 d][68]
    float* sq2 = sm + SM_Q2;
    float* sk1 = sm + SM_K1;   // [32 d][36]
    float* sk2 = sm + SM_K2;
    float* sv  = sm + SM_V;    // [32 k][68]
    float* sp1 = sm + SM_P1;   // [32 k][68 rows]
    float* sp2 = sm + SM_P2;

    int bh = blockIdx.y;
    int q0 = blockIdx.x * 64;
    int tid = threadIdx.x;
    int tr4 = (tid >> 3) * 4;
    int tc  = tid & 7;
    int tc4 = tc * 4;

    const float* Qb = g_Q + (size_t)bh * TT * DH;
    const float* Kb = g_K + (size_t)bh * TT * DH;
    const float* Vb = g_V + (size_t)bh * TT * DH;

    // load Q tile transposed (conflict-free smem stores)
    #pragma unroll
    for (int f = tid; f < 64*16; f += 128){
        int r = f & 63, c4 = f >> 6;
        float4 v = *(const float4*)(Qb + (size_t)(q0 + r)*DH + c4*4);
        float vv[4] = {v.x, v.y, v.z, v.w};
        float* base = (c4 < 8) ? (sq1 + (c4*4)*SQS) : (sq2 + ((c4-8)*4)*SQS);
        #pragma unroll
        for (int j = 0; j < 4; j++) base[j*SQS + r] = vv[j];
    }

    float e1 = 0.f, e2 = 0.f;
    #pragma unroll
    for (int i = 0; i < HD; i++){ e1 += lq1[i]*lk1[i]; e2 += lq2[i]*lk2[i]; }
    float lam = __expf(e1) - __expf(e2) + LAMBDA_INIT;
    float sig_s = fmaxf(sig_s_p[0], 1.0f), sig_n = fmaxf(sig_n_p[0], 1.0f);
    float c1 = -0.5f / (sig_s * sig_s), c2 = -0.5f / (sig_n * sig_n);

    float o1[4][8] = {}, o2[4][8] = {};
    float m1[4], l1[4], m2[4], l2[4];
    #pragma unroll
    for (int i = 0; i < 4; i++){ m1[i] = m2[i] = -1e30f; l1[i] = l2[i] = 0.f; }

    int klo = q0 - BAND; if (klo < 0) klo = 0;
    int khi = q0 + 64 + BAND; if (khi > TT) khi = TT;

    for (int ks = klo; ks < khi; ks += 32){
        __syncthreads();
        // load K transposed + V (conflict-free)
        #pragma unroll
        for (int f = tid; f < 512; f += 128){
            int kk = f & 31, c4 = f >> 5;
            float4 kv = *(const float4*)(Kb + (size_t)(ks + kk)*DH + c4*4);
            float kvv[4] = {kv.x, kv.y, kv.z, kv.w};
            float* base = (c4 < 8) ? (sk1 + (c4*4)*SKS) : (sk2 + ((c4-8)*4)*SKS);
            #pragma unroll
            for (int j = 0; j < 4; j++) base[j*SKS + kk] = kvv[j];
            float4 vv = *(const float4*)(Vb + (size_t)(ks + kk)*DH + c4*4);
            *(float4*)(sv + kk*SVS + c4*4) = vv;
        }
        __syncthreads();

        // scores: 64x32 dual, 4x4 per thread, all-LDS.128
        float s1[4][4] = {}, s2[4][4] = {};
        #pragma unroll 8
        for (int d = 0; d < 32; d++){
            float qa1[4], qa2[4], kb1[4], kb2[4];
            *(float4*)qa1 = *(const float4*)(sq1 + d*SQS + tr4);
            *(float4*)qa2 = *(const float4*)(sq2 + d*SQS + tr4);
            *(float4*)kb1 = *(const float4*)(sk1 + d*SKS + tc4);
            *(float4*)kb2 = *(const float4*)(sk2 + d*SKS + tc4);
            #pragma unroll
            for (int i = 0; i < 4; i++)
                #pragma unroll
                for (int j = 0; j < 4; j++){
                    s1[i][j] += qa1[i]*kb1[j];
                    s2[i][j] += qa2[i]*kb2[j];
                }
        }

        // bias + online softmax; assemble P j-major for float4 stores
        float p1s[4][4], p2s[4][4];   // [j][i]
        #pragma unroll
        for (int i = 0; i < 4; i++){
            int qrow = q0 + tr4 + i;
            float rmax1 = -1e30f, rmax2 = -1e30f;
            #pragma unroll
            for (int j = 0; j < 4; j++){
                float rel = (float)(ks + tc4 + j - qrow);
                float r2 = rel * rel;
                s1[i][j] = s1[i][j]*SCALE + r2*c1;
                s2[i][j] = s2[i][j]*SCALE + r2*c2;
                rmax1 = fmaxf(rmax1, s1[i][j]);
                rmax2 = fmaxf(rmax2, s2[i][j]);
            }
            rmax1 = redmax8(rmax1);
            rmax2 = redmax8(rmax2);
            float mn1 = fmaxf(m1[i], rmax1), mn2 = fmaxf(m2[i], rmax2);
            float sc1 = __expf(m1[i] - mn1), sc2 = __expf(m2[i] - mn2);
            m1[i] = mn1; m2[i] = mn2;
            float rs1 = 0.f, rs2 = 0.f;
            #pragma unroll
            for (int j = 0; j < 4; j++){
                float p1 = __expf(s1[i][j] - mn1);
                float p2 = __expf(s2[i][j] - mn2);
                rs1 += p1; rs2 += p2;
                p1s[j][i] = p1; p2s[j][i] = p2;
            }
            rs1 = redsum8(rs1);
            rs2 = redsum8(rs2);
            l1[i] = l1[i]*sc1 + rs1;
            l2[i] = l2[i]*sc2 + rs2;
            #pragma unroll
            for (int dj = 0; dj < 8; dj++){ o1[i][dj] *= sc1; o2[i][dj] *= sc2; }
        }
        #pragma unroll
        for (int j = 0; j < 4; j++){
            *(float4*)(sp1 + (tc4 + j)*SPS + tr4) = *(float4*)(p1s[j]);
            *(float4*)(sp2 + (tc4 + j)*SPS + tr4) = *(float4*)(p2s[j]);
        }
        __syncthreads();

        // PV: dims {tc4..+3} and {32+tc4..+3}, all-LDS.128
        #pragma unroll 4
        for (int k = 0; k < 32; k++){
            float vv[8], p1v[4], p2v[4];
            *(float4*)(vv)   = *(const float4*)(sv + k*SVS + tc4);
            *(float4*)(vv+4) = *(const float4*)(sv + k*SVS + 32 + tc4);
            *(float4*)p1v = *(const float4*)(sp1 + k*SPS + tr4);
            *(float4*)p2v = *(const float4*)(sp2 + k*SPS + tr4);
            #pragma unroll
            for (int i = 0; i < 4; i++)
                #pragma unroll
                for (int dj = 0; dj < 8; dj++){
                    o1[i][dj] += p1v[i]*vv[dj];
                    o2[i][dj] += p2v[i]*vv[dj];
                }
        }
    }

    // epilogue: combine, head-LN, *0.2, write g_O
    int b_ = bh >> 2, h = bh & 3;
    float wlo[4], whi[4], blo[4], bhi[4];
    *(float4*)wlo = *(const float4*)(hnw + tc4);
    *(float4*)whi = *(const float4*)(hnw + 32 + tc4);
    *(float4*)blo = *(const float4*)(hnb + tc4);
    *(float4*)bhi = *(const float4*)(hnb + 32 + tc4);
    #pragma unroll
    for (int i = 0; i < 4; i++){
        float inv1 = 1.0f / l1[i];
        float inv2 = lam / l2[i];
        float ov[8];
        float s = 0.f;
        #pragma unroll
        for (int dj = 0; dj < 8; dj++){
            ov[dj] = o1[i][dj]*inv1 - o2[i][dj]*inv2;
            s += ov[dj];
        }
        s = redsum8(s);
        float mean = s * (1.0f / DH);
        float sq = 0.f;
        #pragma unroll
        for (int dj = 0; dj < 8; dj++){ float d_ = ov[dj] - mean; sq += d_*d_; }
        sq = redsum8(sq);
        float rstd = rsqrtf(sq * (1.0f / DH) + LN_EPS);
        int qrow = q0 + tr4 + i;
        float* Orow = g_O + ((size_t)(b_*TT + qrow))*256 + h*DH;
        float ylo[4], yhi[4];
        #pragma unroll
        for (int j = 0; j < 4; j++){
            ylo[j] = ((ov[j]   - mean)*rstd*wlo[j] + blo[j]) * (1.0f - LAMBDA_INIT);
            yhi[j] = ((ov[4+j] - mean)*rstd*whi[j] + bhi[j]) * (1.0f - LAMBDA_INIT);
        }
        *(float4*)(Orow + tc4)      = *(float4*)ylo;
        *(float4*)(Orow + 32 + tc4) = *(float4*)yhi;
    }
}

// ================= K3: output GEMM (16384 x 128 x 256) + residual, 64x128x16, 8x8 =================
#define OAS 68
#define OBS 132
__global__ __launch_bounds__(128) void out_gemm(const float* __restrict__ wo,
                                                const float* __restrict__ tokens,
                                                float* __restrict__ out){
    __shared__ float As[16*OAS];   // [k][m 64]
    __shared__ float Bs[16*OBS];   // [k][n 128]
    int brow = blockIdx.x;         // 0..255
    int tid = threadIdx.x;
    int tr = tid >> 4, tc = tid & 15;   // tr 0..7, tc 0..15
    float acc[8][8] = {};

    for (int kc = 0; kc < 16; kc++){
        #pragma unroll
        for (int f = tid; f < 256; f += 128){
            int r = f >> 2, c4 = f & 3;
            float4 v = *(const float4*)(g_O + (size_t)(brow*64 + r)*256 + kc*16 + c4*4);
            As[(c4*4+0)*OAS + r] = v.x;
            As[(c4*4+1)*OAS + r] = v.y;
            As[(c4*4+2)*OAS + r] = v.z;
            As[(c4*4+3)*OAS + r] = v.w;
        }
        #pragma unroll
        for (int f = tid; f < 512; f += 128){
            int kr = f >> 5, c4 = f & 31;
            float4 v = *(const float4*)(wo + (size_t)(kc*16 + kr)*DD + c4*4);
            *(float4*)(Bs + kr*OBS + c4*4) = v;
        }
        __syncthreads();
        #pragma unroll
        for (int k = 0; k < 16; k++){
            float a[8], bbv[8];
            *(float4*)(a)   = *(const float4*)(As + k*OAS + tr*8);
            *(float4*)(a+4) = *(const float4*)(As + k*OAS + tr*8 + 4);
            *(float4*)(bbv)   = *(const float4*)(Bs + k*OBS + tc*8);
            *(float4*)(bbv+4) = *(const float4*)(Bs + k*OBS + tc*8 + 4);
            #pragma unroll
            for (int i = 0; i < 8; i++)
                #pragma unroll
                for (int j = 0; j < 8; j++)
                    acc[i][j] += a[i] * bbv[j];
        }
        __syncthreads();
    }

    #pragma unroll
    for (int i = 0; i < 8; i++){
        int token = brow*64 + tr*8 + i;
        int col = tc*8;
        float4 t0 = *(const float4*)(tokens + (size_t)token*DD + col);
        float4 t1 = *(const float4*)(tokens + (size_t)token*DD + col + 4);
        float4 v0 = make_float4(acc[i][0]+t0.x, acc[i][1]+t0.y, acc[i][2]+t0.z, acc[i][3]+t0.w);
        float4 v1 = make_float4(acc[i][4]+t1.x, acc[i][5]+t1.y, acc[i][6]+t1.z, acc[i][7]+t1.w);
        *(float4*)(out + (size_t)token*DD + col)     = v0;
        *(float4*)(out + (size_t)token*DD + col + 4) = v1;
    }
}

// ================= launch =================
extern "C" void kernel_launch(void* const* d_in, const int* in_sizes, int n_in,
                              void* d_out, int out_size){
    const float* tokens = (const float*)d_in[0];
    const float* ln_w   = (const float*)d_in[1];
    const float* ln_b   = (const float*)d_in[2];
    const float* wq     = (const float*)d_in[3];
    const float* wk     = (const float*)d_in[4];
    const float* wv     = (const float*)d_in[5];
    const float* wo     = (const float*)d_in[6];
    const float* lq1    = (const float*)d_in[7];
    const float* lk1    = (const float*)d_in[8];
    const float* lq2    = (const float*)d_in[9];
    const float* lk2    = (const float*)d_in[10];
    const float* sig_s  = (const float*)d_in[11];
    const float* sig_n  = (const float*)d_in[12];
    const float* hnw    = (const float*)d_in[13];
    const float* hnb    = (const float*)d_in[14];
    float* out = (float*)d_out;

    cudaFuncSetAttribute(attn_kernel, cudaFuncAttributeMaxDynamicSharedMemorySize,
                         ATTN_SMEM_BYTES);

    ln_kernel<<<NTOK/8, dim3(32,8)>>>(tokens, ln_w, ln_b);
    qkv_gemm<<<dim3(NTOK/128, 6), 256>>>(wq, wk, wv);
    attn_kernel<<<dim3(TT/64, BB*HH), 128, ATTN_SMEM_BYTES>>>(
        lq1, lk1, lq2, lk2, sig_s, sig_n, hnw, hnb);
    out_gemm<<<NTOK/64, 128>>>(wo, tokens, out);
}

// round 3
// speedup vs baseline: 2.4790x; 2.4790x over previous
#include <cuda_runtime.h>
#include <cuda_bf16.h>
#include <math.h>
#include <stdint.h>

// ---------------- problem constants ----------------
#define BB 8
#define TT 2048
#define DD 128
#define HH 4
#define HD 32
#define DH 64
#define NTOK (BB*TT)
#define SCALE 0.17677669529663687f
#define LAMBDA_INIT 0.8f
#define LN_EPS 1e-5f
#define BAND 96

// ---------------- scratch ----------------
__device__ float g_xnorm[NTOK * DD];
__device__ float g_Q[BB*HH*TT*DH];
__device__ float g_K[BB*HH*TT*DH];
__device__ float g_V[BB*HH*TT*DH];
__device__ float g_O[NTOK * 256];

// ---------------- tf32 helpers ----------------
__device__ __forceinline__ uint32_t f2tf(float x){
    uint32_t r; asm("cvt.rna.tf32.f32 %0, %1;" : "=r"(r) : "f"(x)); return r;
}
__device__ __forceinline__ float tfr(float x){ return __uint_as_float(f2tf(x)); }

__device__ __forceinline__ void mma8(float4& d, const uint32_t* a, const uint32_t* b, const float4& c){
    asm volatile("mma.sync.aligned.m16n8k8.row.col.f32.tf32.tf32.f32 "
        "{%0,%1,%2,%3}, {%4,%5,%6,%7}, {%8,%9}, {%10,%11,%12,%13};"
        : "=f"(d.x),"=f"(d.y),"=f"(d.z),"=f"(d.w)
        : "r"(a[0]),"r"(a[1]),"r"(a[2]),"r"(a[3]),
          "r"(b[0]),"r"(b[1]),
          "f"(c.x),"f"(c.y),"f"(c.z),"f"(c.w));
}

// ================= K0: layernorm =================
__global__ __launch_bounds__(256) void ln_kernel(const float* __restrict__ x,
                                                 const float* __restrict__ w,
                                                 const float* __restrict__ b){
    int token = blockIdx.x * 8 + threadIdx.y;
    int lane  = threadIdx.x;
    const float4* xr = (const float4*)(x + (size_t)token * DD);
    float4 v = xr[lane];
    float s = v.x + v.y + v.z + v.w;
    #pragma unroll
    for (int o = 16; o; o >>= 1) s += __shfl_xor_sync(0xffffffffu, s, o);
    float mu = s * (1.0f / DD);
    float dx0 = v.x - mu, dx1 = v.y - mu, dx2 = v.z - mu, dx3 = v.w - mu;
    float sq = dx0*dx0 + dx1*dx1 + dx2*dx2 + dx3*dx3;
    #pragma unroll
    for (int o = 16; o; o >>= 1) sq += __shfl_xor_sync(0xffffffffu, sq, o);
    float rstd = rsqrtf(sq * (1.0f / DD) + LN_EPS);
    float4 wv = ((const float4*)w)[lane];
    float4 bv = ((const float4*)b)[lane];
    float4 out;
    out.x = dx0 * rstd * wv.x + bv.x;
    out.y = dx1 * rstd * wv.y + bv.y;
    out.z = dx2 * rstd * wv.z + bv.z;
    out.w = dx3 * rstd * wv.w + bv.w;
    ((float4*)(g_xnorm + (size_t)token * DD))[lane] = out;
}

// ================= K1: QKV GEMM tf32 mma (16384 x 768 x 128) =================
// block 256 thr (8 warps), tile 128x128, BK=32 x 4 stages. Warp 64x32.
__global__ __launch_bounds__(256) void qkv_gemm(const float* __restrict__ wq,
                                                const float* __restrict__ wk,
                                                const float* __restrict__ wv){
    __shared__ float sA[128*36];   // [m][k] stride 36
    __shared__ float sB[32*136];   // [k][n] stride 136
    int brow = blockIdx.x, bc = blockIdx.y;
    int tid = threadIdx.x;
    int w = tid >> 5, lane = tid & 31, g = lane >> 2, q = lane & 3;
    int wm = w >> 2, wn = w & 3;
    const float* W = (bc < 2) ? wq : (bc < 4 ? wk : wv);
    int colbase = (bc & 1) * 128;
    float4 acc[4][4];
    #pragma unroll
    for (int i = 0; i < 4; i++)
        #pragma unroll
        for (int j = 0; j < 4; j++) acc[i][j] = make_float4(0.f,0.f,0.f,0.f);

    for (int kc = 0; kc < 4; kc++){
        #pragma unroll
        for (int f = tid; f < 1024; f += 256){
            int r = f >> 3, c4 = f & 7;
            float4 v = *(const float4*)(g_xnorm + (size_t)(brow*128 + r)*DD + kc*32 + c4*4);
            float* d = sA + r*36 + c4*4;
            d[0]=tfr(v.x); d[1]=tfr(v.y); d[2]=tfr(v.z); d[3]=tfr(v.w);
        }
        #pragma unroll
        for (int f = tid; f < 1024; f += 256){
            int kr = f >> 5, c4 = f & 31;
            float4 v = *(const float4*)(W + (size_t)(kc*32 + kr)*256 + colbase + c4*4);
            float* d = sB + kr*136 + c4*4;
            d[0]=tfr(v.x); d[1]=tfr(v.y); d[2]=tfr(v.z); d[3]=tfr(v.w);
        }
        __syncthreads();
        #pragma unroll
        for (int ks = 0; ks < 4; ks++){
            uint32_t a[4][4];
            int kk = ks*8 + q;
            #pragma unroll
            for (int mt = 0; mt < 4; mt++){
                int r = wm*64 + mt*16 + g;
                a[mt][0] = __float_as_uint(sA[r*36 + kk]);
                a[mt][1] = __float_as_uint(sA[(r+8)*36 + kk]);
                a[mt][2] = __float_as_uint(sA[r*36 + kk + 4]);
                a[mt][3] = __float_as_uint(sA[(r+8)*36 + kk + 4]);
            }
            #pragma unroll
            for (int nt = 0; nt < 4; nt++){
                uint32_t b[2];
                int n = wn*32 + nt*8 + g;
                b[0] = __float_as_uint(sB[kk*136 + n]);
                b[1] = __float_as_uint(sB[(kk+4)*136 + n]);
                #pragma unroll
                for (int mt = 0; mt < 4; mt++)
                    mma8(acc[mt][nt], a[mt], b, acc[mt][nt]);
            }
        }
        __syncthreads();
    }

    int mat = bc >> 1;
    float* dst = (mat == 0) ? g_Q : (mat == 1 ? g_K : g_V);
    #pragma unroll
    for (int mt = 0; mt < 4; mt++){
        int r0 = brow*128 + wm*64 + mt*16 + g;
        int r1 = r0 + 8;
        int b0_ = r0 >> 11, t0 = r0 & (TT-1);
        int b1_ = r1 >> 11, t1 = r1 & (TT-1);
        #pragma unroll
        for (int nt = 0; nt < 4; nt++){
            int col = colbase + wn*32 + nt*8 + 2*q;
            int head = col >> 6, dim = col & 63;
            float* p0 = dst + ((size_t)((b0_*HH + head)*TT + t0))*DH + dim;
            float* p1 = dst + ((size_t)((b1_*HH + head)*TT + t1))*DH + dim;
            *(float2*)p0 = make_float2(acc[mt][nt].x, acc[mt][nt].y);
            *(float2*)p1 = make_float2(acc[mt][nt].z, acc[mt][nt].w);
        }
    }
}

// ================= K2: banded dual-softmax flash attention, tf32 mma =================
// block 128 thr (4 warps), 64 q-rows per block, warp owns 16 rows.
__global__ __launch_bounds__(128) void attn_kernel(
        const float* __restrict__ lq1, const float* __restrict__ lk1,
        const float* __restrict__ lq2, const float* __restrict__ lk2,
        const float* __restrict__ sig_s_p, const float* __restrict__ sig_n_p,
        const float* __restrict__ hnw, const float* __restrict__ hnb){
    __shared__ float sQ[64*68];   // [row][dim] stride 68, tf32
    __shared__ float sK[32*68];   // [key][dim] stride 68
    __shared__ float sV[32*72];   // [key][dim] stride 72

    int bh = blockIdx.y;
    int q0 = blockIdx.x * 64;
    int tid = threadIdx.x;
    int w = tid >> 5, lane = tid & 31, g = lane >> 2, q = lane & 3;

    const float* Qb = g_Q + (size_t)bh * TT * DH;
    const float* Kb = g_K + (size_t)bh * TT * DH;
    const float* Vb = g_V + (size_t)bh * TT * DH;

    // Q tile fill (tf32)
    #pragma unroll
    for (int f = tid; f < 1024; f += 128){
        int r = f >> 4, c4 = f & 15;
        float4 v = *(const float4*)(Qb + (size_t)(q0 + r)*DH + c4*4);
        float* d = sQ + r*68 + c4*4;
        d[0]=tfr(v.x); d[1]=tfr(v.y); d[2]=tfr(v.z); d[3]=tfr(v.w);
    }

    float e1 = 0.f, e2 = 0.f;
    #pragma unroll
    for (int i = 0; i < HD; i++){ e1 += lq1[i]*lk1[i]; e2 += lq2[i]*lk2[i]; }
    float lam = __expf(e1) - __expf(e2) + LAMBDA_INIT;
    float sig_s = fmaxf(sig_s_p[0], 1.0f), sig_n = fmaxf(sig_n_p[0], 1.0f);
    float c1 = -0.5f / (sig_s * sig_s), c2 = -0.5f / (sig_n * sig_n);

    // O^T accumulators: [mt][j]; cols (q-rows) j*8 + 2q, 2q+1; rows (dims) mt*16+g, +8
    float4 o1[4][2], o2[4][2];
    #pragma unroll
    for (int mt = 0; mt < 4; mt++)
        #pragma unroll
        for (int j = 0; j < 2; j++){
            o1[mt][j] = make_float4(0.f,0.f,0.f,0.f);
            o2[mt][j] = make_float4(0.f,0.f,0.f,0.f);
        }
    float m1lo = -1e30f, m1hi = -1e30f, m2lo = -1e30f, m2hi = -1e30f;
    float l1lo = 0.f, l1hi = 0.f, l2lo = 0.f, l2hi = 0.f;

    float row_lo = (float)(q0 + w*16 + g);
    float row_hi = row_lo + 8.0f;

    int klo = q0 - BAND; if (klo < 0) klo = 0;
    int khi = q0 + 64 + BAND; if (khi > TT) khi = TT;

    for (int ksb = klo; ksb < khi; ksb += 32){
        __syncthreads();
        // K/V tile fill (tf32)
        #pragma unroll
        for (int f = tid; f < 512; f += 128){
            int kk = f >> 4, c4 = f & 15;
            float4 kv = *(const float4*)(Kb + (size_t)(ksb + kk)*DH + c4*4);
            float* kd = sK + kk*68 + c4*4;
            kd[0]=tfr(kv.x); kd[1]=tfr(kv.y); kd[2]=tfr(kv.z); kd[3]=tfr(kv.w);
            float4 vv = *(const float4*)(Vb + (size_t)(ksb + kk)*DH + c4*4);
            float* vd = sV + kk*72 + c4*4;
            vd[0]=tfr(vv.x); vd[1]=tfr(vv.y); vd[2]=tfr(vv.z); vd[3]=tfr(vv.w);
        }
        __syncthreads();

        // ---- scores: S = Q K^T, 16x32 per warp per branch ----
        float4 s1[4], s2[4];
        #pragma unroll
        for (int nt = 0; nt < 4; nt++){ s1[nt] = make_float4(0.f,0.f,0.f,0.f); s2[nt] = s1[nt]; }
        #pragma unroll
        for (int ks = 0; ks < 4; ks++){
            uint32_t a1[4], a2[4];
            int rbase = (w*16 + g)*68;
            int d0 = ks*8 + q;
            a1[0] = __float_as_uint(sQ[rbase + d0]);
            a1[1] = __float_as_uint(sQ[rbase + 8*68 + d0]);
            a1[2] = __float_as_uint(sQ[rbase + d0 + 4]);
            a1[3] = __float_as_uint(sQ[rbase + 8*68 + d0 + 4]);
            a2[0] = __float_as_uint(sQ[rbase + d0 + 32]);
            a2[1] = __float_as_uint(sQ[rbase + 8*68 + d0 + 32]);
            a2[2] = __float_as_uint(sQ[rbase + d0 + 36]);
            a2[3] = __float_as_uint(sQ[rbase + 8*68 + d0 + 36]);
            #pragma unroll
            for (int nt = 0; nt < 4; nt++){
                uint32_t b1[2], b2[2];
                int kb = (nt*8 + g)*68 + d0;
                b1[0] = __float_as_uint(sK[kb]);
                b1[1] = __float_as_uint(sK[kb + 4]);
                b2[0] = __float_as_uint(sK[kb + 32]);
                b2[1] = __float_as_uint(sK[kb + 36]);
                mma8(s1[nt], a1, b1, s1[nt]);
                mma8(s2[nt], a2, b2, s2[nt]);
            }
        }

        // ---- bias + online softmax on C-fragments ----
        float rm1lo = -1e30f, rm1hi = -1e30f, rm2lo = -1e30f, rm2hi = -1e30f;
        #pragma unroll
        for (int nt = 0; nt < 4; nt++){
            float k0f = (float)(ksb + nt*8 + 2*q);
            float rx_lo = k0f - row_lo,   ry_lo = k0f + 1.0f - row_lo;
            float rx_hi = k0f - row_hi,   ry_hi = k0f + 1.0f - row_hi;
            s1[nt].x = s1[nt].x*SCALE + rx_lo*rx_lo*c1;
            s1[nt].y = s1[nt].y*SCALE + ry_lo*ry_lo*c1;
            s1[nt].z = s1[nt].z*SCALE + rx_hi*rx_hi*c1;
            s1[nt].w = s1[nt].w*SCALE + ry_hi*ry_hi*c1;
            s2[nt].x = s2[nt].x*SCALE + rx_lo*rx_lo*c2;
            s2[nt].y = s2[nt].y*SCALE + ry_lo*ry_lo*c2;
            s2[nt].z = s2[nt].z*SCALE + rx_hi*rx_hi*c2;
            s2[nt].w = s2[nt].w*SCALE + ry_hi*ry_hi*c2;
            rm1lo = fmaxf(rm1lo, fmaxf(s1[nt].x, s1[nt].y));
            rm1hi = fmaxf(rm1hi, fmaxf(s1[nt].z, s1[nt].w));
            rm2lo = fmaxf(rm2lo, fmaxf(s2[nt].x, s2[nt].y));
            rm2hi = fmaxf(rm2hi, fmaxf(s2[nt].z, s2[nt].w));
        }
        #pragma unroll
        for (int o = 1; o <= 2; o <<= 1){
            rm1lo = fmaxf(rm1lo, __shfl_xor_sync(0xffffffffu, rm1lo, o));
            rm1hi = fmaxf(rm1hi, __shfl_xor_sync(0xffffffffu, rm1hi, o));
            rm2lo = fmaxf(rm2lo, __shfl_xor_sync(0xffffffffu, rm2lo, o));
            rm2hi = fmaxf(rm2hi, __shfl_xor_sync(0xffffffffu, rm2hi, o));
        }
        float mn1lo = fmaxf(m1lo, rm1lo), mn1hi = fmaxf(m1hi, rm1hi);
        float mn2lo = fmaxf(m2lo, rm2lo), mn2hi = fmaxf(m2hi, rm2hi);
        float sc1lo = __expf(m1lo - mn1lo), sc1hi = __expf(m1hi - mn1hi);
        float sc2lo = __expf(m2lo - mn2lo), sc2hi = __expf(m2hi - mn2hi);
        m1lo = mn1lo; m1hi = mn1hi; m2lo = mn2lo; m2hi = mn2hi;

        float rs1lo = 0.f, rs1hi = 0.f, rs2lo = 0.f, rs2hi = 0.f;
        float4 p1[4], p2[4];
        #pragma unroll
        for (int nt = 0; nt < 4; nt++){
            p1[nt].x = tfr(__expf(s1[nt].x - mn1lo));
            p1[nt].y = tfr(__expf(s1[nt].y - mn1lo));
            p1[nt].z = tfr(__expf(s1[nt].z - mn1hi));
            p1[nt].w = tfr(__expf(s1[nt].w - mn1hi));
            p2[nt].x = tfr(__expf(s2[nt].x - mn2lo));
            p2[nt].y = tfr(__expf(s2[nt].y - mn2lo));
            p2[nt].z = tfr(__expf(s2[nt].z - mn2hi));
            p2[nt].w = tfr(__expf(s2[nt].w - mn2hi));
            rs1lo += p1[nt].x + p1[nt].y;  rs1hi += p1[nt].z + p1[nt].w;
            rs2lo += p2[nt].x + p2[nt].y;  rs2hi += p2[nt].z + p2[nt].w;
        }
        #pragma unroll
        for (int o = 1; o <= 2; o <<= 1){
            rs1lo += __shfl_xor_sync(0xffffffffu, rs1lo, o);
            rs1hi += __shfl_xor_sync(0xffffffffu, rs1hi, o);
            rs2lo += __shfl_xor_sync(0xffffffffu, rs2lo, o);
            rs2hi += __shfl_xor_sync(0xffffffffu, rs2hi, o);
        }
        l1lo = l1lo*sc1lo + rs1lo;  l1hi = l1hi*sc1hi + rs1hi;
        l2lo = l2lo*sc2lo + rs2lo;  l2hi = l2hi*sc2hi + rs2hi;

        // broadcast per-column (q-row) rescale factors for O^T
        int src0c = 8*q, src1c = 8*q + 4;
        float sA0 = __shfl_sync(0xffffffffu, sc1lo, src0c);
        float sA1 = __shfl_sync(0xffffffffu, sc1lo, src1c);
        float sA2 = __shfl_sync(0xffffffffu, sc1hi, src0c);
        float sA3 = __shfl_sync(0xffffffffu, sc1hi, src1c);
        float sB0 = __shfl_sync(0xffffffffu, sc2lo, src0c);
        float sB1 = __shfl_sync(0xffffffffu, sc2lo, src1c);
        float sB2 = __shfl_sync(0xffffffffu, sc2hi, src0c);
        float sB3 = __shfl_sync(0xffffffffu, sc2hi, src1c);
        #pragma unroll
        for (int mt = 0; mt < 4; mt++){
            o1[mt][0].x *= sA0; o1[mt][0].y *= sA1; o1[mt][0].z *= sA0; o1[mt][0].w *= sA1;
            o1[mt][1].x *= sA2; o1[mt][1].y *= sA3; o1[mt][1].z *= sA2; o1[mt][1].w *= sA3;
            o2[mt][0].x *= sB0; o2[mt][0].y *= sB1; o2[mt][0].z *= sB0; o2[mt][0].w *= sB1;
            o2[mt][1].x *= sB2; o2[mt][1].y *= sB3; o2[mt][1].z *= sB2; o2[mt][1].w *= sB3;
        }

        // ---- PV transposed: O^T += V^T · P^T ----
        #pragma unroll
        for (int ks = 0; ks < 4; ks++){
            int s0 = 4*g + (q >> 1);
            int s1i = s0 + 2;
            float x0 = __shfl_sync(0xffffffffu, p1[ks].x, s0);
            float y0 = __shfl_sync(0xffffffffu, p1[ks].y, s0);
            float z0 = __shfl_sync(0xffffffffu, p1[ks].z, s0);
            float w0 = __shfl_sync(0xffffffffu, p1[ks].w, s0);
            float x1 = __shfl_sync(0xffffffffu, p1[ks].x, s1i);
            float y1 = __shfl_sync(0xffffffffu, p1[ks].y, s1i);
            float z1 = __shfl_sync(0xffffffffu, p1[ks].z, s1i);
            float w1 = __shfl_sync(0xffffffffu, p1[ks].w, s1i);
            float u0 = __shfl_sync(0xffffffffu, p2[ks].x, s0);
            float v0 = __shfl_sync(0xffffffffu, p2[ks].y, s0);
            float t0 = __shfl_sync(0xffffffffu, p2[ks].z, s0);
            float r0 = __shfl_sync(0xffffffffu, p2[ks].w, s0);
            float u1 = __shfl_sync(0xffffffffu, p2[ks].x, s1i);
            float v1 = __shfl_sync(0xffffffffu, p2[ks].y, s1i);
            float t1 = __shfl_sync(0xffffffffu, p2[ks].z, s1i);
            float r1 = __shfl_sync(0xffffffffu, p2[ks].w, s1i);
            bool odd = (q & 1);
            uint32_t b1j0[2] = { __float_as_uint(odd ? y0 : x0), __float_as_uint(odd ? y1 : x1) };
            uint32_t b1j1[2] = { __float_as_uint(odd ? w0 : z0), __float_as_uint(odd ? w1 : z1) };
            uint32_t b2j0[2] = { __float_as_uint(odd ? v0 : u0), __float_as_uint(odd ? v1 : u1) };
            uint32_t b2j1[2] = { __float_as_uint(odd ? r0 : t0), __float_as_uint(odd ? r1 : t1) };
            #pragma unroll
            for (int mt = 0; mt < 4; mt++){
                uint32_t a[4];
                int k0 = ks*8 + q, d0 = mt*16 + g;
                a[0] = __float_as_uint(sV[k0*72 + d0]);
                a[1] = __float_as_uint(sV[k0*72 + d0 + 8]);
                a[2] = __float_as_uint(sV[(k0+4)*72 + d0]);
                a[3] = __float_as_uint(sV[(k0+4)*72 + d0 + 8]);
                mma8(o1[mt][0], a, b1j0, o1[mt][0]);
                mma8(o1[mt][1], a, b1j1, o1[mt][1]);
                mma8(o2[mt][0], a, b2j0, o2[mt][0]);
                mma8(o2[mt][1], a, b2j1, o2[mt][1]);
            }
        }
    }

    // ---- epilogue: combine branches, head-LN per q-row, scale, store ----
    float il1lo = 1.0f / l1lo, il1hi = 1.0f / l1hi;
    float il2lo = lam / l2lo,  il2hi = lam / l2hi;
    int src0c = 8*q, src1c = 8*q + 4;
    float A0 = __shfl_sync(0xffffffffu, il1lo, src0c);
    float A1 = __shfl_sync(0xffffffffu, il1lo, src1c);
    float A2 = __shfl_sync(0xffffffffu, il1hi, src0c);
    float A3 = __shfl_sync(0xffffffffu, il1hi, src1c);
    float B0 = __shfl_sync(0xffffffffu, il2lo, src0c);
    float B1 = __shfl_sync(0xffffffffu, il2lo, src1c);
    float B2 = __shfl_sync(0xffffffffu, il2hi, src0c);
    float B3 = __shfl_sync(0xffffffffu, il2hi, src1c);

    float4 ov[4][2];
    #pragma unroll
    for (int mt = 0; mt < 4; mt++){
        ov[mt][0].x = o1[mt][0].x*A0 - o2[mt][0].x*B0;
        ov[mt][0].y = o1[mt][0].y*A1 - o2[mt][0].y*B1;
        ov[mt][0].z = o1[mt][0].z*A0 - o2[mt][0].z*B0;
        ov[mt][0].w = o1[mt][0].w*A1 - o2[mt][0].w*B1;
        ov[mt][1].x = o1[mt][1].x*A2 - o2[mt][1].x*B2;
        ov[mt][1].y = o1[mt][1].y*A3 - o2[mt][1].y*B3;
        ov[mt][1].z = o1[mt][1].z*A2 - o2[mt][1].z*B2;
        ov[mt][1].w = o1[mt][1].w*A3 - o2[mt][1].w*B3;
    }
    // per-column LN over 64 dims (8 in-thread, reduce over g via xor 4/8/16)
    float cs[4] = {0.f,0.f,0.f,0.f};
    #pragma unroll
    for (int mt = 0; mt < 4; mt++){
        cs[0] += ov[mt][0].x + ov[mt][0].z;
        cs[1] += ov[mt][0].y + ov[mt][0].w;
        cs[2] += ov[mt][1].x + ov[mt][1].z;
        cs[3] += ov[mt][1].y + ov[mt][1].w;
    }
    #pragma unroll
    for (int o = 4; o <= 16; o <<= 1)
        #pragma unroll
        for (int i = 0; i < 4; i++) cs[i] += __shfl_xor_sync(0xffffffffu, cs[i], o);
    float mean[4];
    #pragma unroll
    for (int i = 0; i < 4; i++) mean[i] = cs[i] * (1.0f / DH);
    float vs[4] = {0.f,0.f,0.f,0.f};
    #pragma unroll
    for (int mt = 0; mt < 4; mt++){
        float d0, d1;
        d0 = ov[mt][0].x - mean[0]; d1 = ov[mt][0].z - mean[0]; vs[0] += d0*d0 + d1*d1;
        d0 = ov[mt][0].y - mean[1]; d1 = ov[mt][0].w - mean[1]; vs[1] += d0*d0 + d1*d1;
        d0 = ov[mt][1].x - mean[2]; d1 = ov[mt][1].z - mean[2]; vs[2] += d0*d0 + d1*d1;
        d0 = ov[mt][1].y - mean[3]; d1 = ov[mt][1].w - mean[3]; vs[3] += d0*d0 + d1*d1;
    }
    #pragma unroll
    for (int o = 4; o <= 16; o <<= 1)
        #pragma unroll
        for (int i = 0; i < 4; i++) vs[i] += __shfl_xor_sync(0xffffffffu, vs[i], o);
    float rstd[4];
    #pragma unroll
    for (int i = 0; i < 4; i++) rstd[i] = rsqrtf(vs[i] * (1.0f / DH) + LN_EPS);

    float wv_[8], bv_[8];
    #pragma unroll
    for (int mt = 0; mt < 4; mt++){
        wv_[2*mt]   = hnw[mt*16 + g];
        wv_[2*mt+1] = hnw[mt*16 + g + 8];
        bv_[2*mt]   = hnb[mt*16 + g];
        bv_[2*mt+1] = hnb[mt*16 + g + 8];
    }
    int b_ = bh >> 2, h = bh & 3;
    int tokbase = b_*TT + q0 + w*16;
    #pragma unroll
    for (int j = 0; j < 2; j++){
        #pragma unroll
        for (int c = 0; c < 2; c++){
            int colk = j*2 + c;
            int token = tokbase + j*8 + 2*q + c;
            float* Od = g_O + (size_t)token*256 + h*DH;
            float mu = mean[colk], rs = rstd[colk];
            #pragma unroll
            for (int mt = 0; mt < 4; mt++){
                float e0 = c ? ov[mt][j].y : ov[mt][j].x;
                float e1 = c ? ov[mt][j].w : ov[mt][j].z;
                Od[mt*16 + g]     = ((e0 - mu)*rs*wv_[2*mt]   + bv_[2*mt])   * (1.0f - LAMBDA_INIT);
                Od[mt*16 + g + 8] = ((e1 - mu)*rs*wv_[2*mt+1] + bv_[2*mt+1]) * (1.0f - LAMBDA_INIT);
            }
        }
    }
}

// ================= K3: output GEMM tf32 mma (16384 x 128 x 256) + residual =================
__global__ __launch_bounds__(256) void out_gemm(const float* __restrict__ wo,
                                                const float* __restrict__ tokens,
                                                float* __restrict__ out){
    __shared__ float sA[128*36];
    __shared__ float sB[32*136];
    int brow = blockIdx.x;
    int tid = threadIdx.x;
    int w = tid >> 5, lane = tid & 31, g = lane >> 2, q = lane & 3;
    int wm = w >> 2, wn = w & 3;
    float4 acc[4][4];
    #pragma unroll
    for (int i = 0; i < 4; i++)
        #pragma unroll
        for (int j = 0; j < 4; j++) acc[i][j] = make_float4(0.f,0.f,0.f,0.f);

    for (int kc = 0; kc < 8; kc++){
        #pragma unroll
        for (int f = tid; f < 1024; f += 256){
            int r = f >> 3, c4 = f & 7;
            float4 v = *(const float4*)(g_O + (size_t)(brow*128 + r)*256 + kc*32 + c4*4);
            float* d = sA + r*36 + c4*4;
            d[0]=tfr(v.x); d[1]=tfr(v.y); d[2]=tfr(v.z); d[3]=tfr(v.w);
        }
        #pragma unroll
        for (int f = tid; f < 1024; f += 256){
            int kr = f >> 5, c4 = f & 31;
            float4 v = *(const float4*)(wo + (size_t)(kc*32 + kr)*DD + c4*4);
            float* d = sB + kr*136 + c4*4;
            d[0]=tfr(v.x); d[1]=tfr(v.y); d[2]=tfr(v.z); d[3]=tfr(v.w);
        }
        __syncthreads();
        #pragma unroll
        for (int ks = 0; ks < 4; ks++){
            uint32_t a[4][4];
            int kk = ks*8 + q;
            #pragma unroll
            for (int mt = 0; mt < 4; mt++){
                int r = wm*64 + mt*16 + g;
                a[mt][0] = __float_as_uint(sA[r*36 + kk]);
                a[mt][1] = __float_as_uint(sA[(r+8)*36 + kk]);
                a[mt][2] = __float_as_uint(sA[r*36 + kk + 4]);
                a[mt][3] = __float_as_uint(sA[(r+8)*36 + kk + 4]);
            }
            #pragma unroll
            for (int nt = 0; nt < 4; nt++){
                uint32_t b[2];
                int n = wn*32 + nt*8 + g;
                b[0] = __float_as_uint(sB[kk*136 + n]);
                b[1] = __float_as_uint(sB[(kk+4)*136 + n]);
                #pragma unroll
                for (int mt = 0; mt < 4; mt++)
                    mma8(acc[mt][nt], a[mt], b, acc[mt][nt]);
            }
        }
        __syncthreads();
    }

    #pragma unroll
    for (int mt = 0; mt < 4; mt++){
        int r0 = brow*128 + wm*64 + mt*16 + g;
        int r1 = r0 + 8;
        #pragma unroll
        for (int nt = 0; nt < 4; nt++){
            int col = wn*32 + nt*8 + 2*q;
            float2 t0 = *(const float2*)(tokens + (size_t)r0*DD + col);
            float2 t1 = *(const float2*)(tokens + (size_t)r1*DD + col);
            *(float2*)(out + (size_t)r0*DD + col) = make_float2(acc[mt][nt].x + t0.x, acc[mt][nt].y + t0.y);
            *(float2*)(out + (size_t)r1*DD + col) = make_float2(acc[mt][nt].z + t1.x, acc[mt][nt].w + t1.y);
        }
    }
}

// ================= launch =================
extern "C" void kernel_launch(void* const* d_in, const int* in_sizes, int n_in,
                              void* d_out, int out_size){
    const float* tokens = (const float*)d_in[0];
    const float* ln_w   = (const float*)d_in[1];
    const float* ln_b   = (const float*)d_in[2];
    const float* wq     = (const float*)d_in[3];
    const float* wk     = (const float*)d_in[4];
    const float* wv     = (const float*)d_in[5];
    const float* wo     = (const float*)d_in[6];
    const float* lq1    = (const float*)d_in[7];
    const float* lk1    = (const float*)d_in[8];
    const float* lq2    = (const float*)d_in[9];
    const float* lk2    = (const float*)d_in[10];
    const float* sig_s  = (const float*)d_in[11];
    const float* sig_n  = (const float*)d_in[12];
    const float* hnw    = (const float*)d_in[13];
    const float* hnb    = (const float*)d_in[14];
    float* out = (float*)d_out;

    ln_kernel<<<NTOK/8, dim3(32,8)>>>(tokens, ln_w, ln_b);
    qkv_gemm<<<dim3(NTOK/128, 6), 256>>>(wq, wk, wv);
    attn_kernel<<<dim3(TT/64, BB*HH), 128>>>(lq1, lk1, lq2, lk2, sig_s, sig_n, hnw, hnb);
    out_gemm<<<NTOK/128, 256>>>(wo, tokens, out);
}